// round 1
// baseline (speedup 1.0000x reference)
#include <cuda_runtime.h>

typedef unsigned long long u64;

#define NGATES 12
// For each gate g (layer*4+qubit), element e in {u00,u01,u10,u11}:
// 3 packed u64 constants: (re,re), (im,im), (-im,-im)
__device__ u64 g_gates[NGATES * 12];

// ---------- packed f32x2 helpers ----------
__device__ __forceinline__ u64 pk2(float a, float b) {
    u64 r; asm("mov.b64 %0, {%1, %2};" : "=l"(r) : "f"(a), "f"(b)); return r;
}
__device__ __forceinline__ void upk2(u64 v, float& a, float& b) {
    asm("mov.b64 {%0, %1}, %2;" : "=f"(a), "=f"(b) : "l"(v));
}
__device__ __forceinline__ u64 f2fma(u64 a, u64 b, u64 c) {
    u64 d; asm("fma.rn.f32x2 %0, %1, %2, %3;" : "=l"(d) : "l"(a), "l"(b), "l"(c)); return d;
}
__device__ __forceinline__ u64 f2mul(u64 a, u64 b) {
    u64 d; asm("mul.rn.f32x2 %0, %1, %2;" : "=l"(d) : "l"(a), "l"(b)); return d;
}
__device__ __forceinline__ u64 f2add(u64 a, u64 b) {
    u64 d; asm("add.rn.f32x2 %0, %1, %2;" : "=l"(d) : "l"(a), "l"(b)); return d;
}
__device__ __forceinline__ u64 f2neg(u64 a) { return a ^ 0x8000000080000000ULL; }

// packed complex: r = (reA, reB), i = (imA, imB) — two samples per thread
struct C2 { u64 r, i; };

// per-sample complex multiply (both operands packed-by-sample)
__device__ __forceinline__ C2 cmul(const C2& a, const C2& b) {
    C2 o;
    o.r = f2fma(f2neg(a.i), b.i, f2mul(a.r, b.r));
    o.i = f2fma(a.i, b.r, f2mul(a.r, b.i));
    return o;
}
// z *= u where u is a uniform gate constant given as (rr, ii, -ii) dup-packed
__device__ __forceinline__ C2 cmulc(u64 ur, u64 ui, u64 uni, const C2& z) {
    C2 o;
    o.r = f2fma(uni, z.i, f2mul(ur, z.r));
    o.i = f2fma(ur, z.i, f2mul(ui, z.r));
    return o;
}
__device__ __forceinline__ void cfmac(C2& acc, u64 ur, u64 ui, u64 uni, const C2& z) {
    acc.r = f2fma(ur, z.r, acc.r);
    acc.r = f2fma(uni, z.i, acc.r);
    acc.i = f2fma(ui, z.r, acc.i);
    acc.i = f2fma(ur, z.i, acc.i);
}

// ---------- prep: 12 Rot matrices from q_weights ----------
// Rot(phi,theta,omega) = RZ(omega) @ RY(theta) @ RZ(phi)
// U00 = cos(t/2) e^{-i(phi+omega)/2}; U01 = -sin(t/2) e^{ i(phi-omega)/2}
// U10 = sin(t/2) e^{-i(phi-omega)/2}; U11 =  cos(t/2) e^{ i(phi+omega)/2}
__global__ void prep_kernel(const float* __restrict__ qw) {
    int g = threadIdx.x;
    if (g >= NGATES) return;
    float phi = qw[3 * g + 0], th = qw[3 * g + 1], om = qw[3 * g + 2];
    float s, c; sincosf(0.5f * th, &s, &c);
    float a = 0.5f * (phi + om), b = 0.5f * (phi - om);
    float sa, ca, sb, cb;
    sincosf(a, &sa, &ca);
    sincosf(b, &sb, &cb);
    float re[4], im[4];
    re[0] =  c * ca;  im[0] = -c * sa;
    re[1] = -s * cb;  im[1] = -s * sb;
    re[2] =  s * cb;  im[2] = -s * sb;
    re[3] =  c * ca;  im[3] =  c * sa;
#pragma unroll
    for (int e = 0; e < 4; e++) {
        g_gates[g * 12 + e * 3 + 0] = pk2(re[e], re[e]);
        g_gates[g * 12 + e * 3 + 1] = pk2(im[e], im[e]);
        g_gates[g * 12 + e * 3 + 2] = pk2(-im[e], -im[e]);
    }
}

// ---------- main kernel: 2 samples per thread, lane-packed ----------
__global__ void __launch_bounds__(256) qlayer_kernel(const float* __restrict__ x,
                                                     float* __restrict__ out,
                                                     int half) {
    __shared__ u64 sg[NGATES * 12];
    int tid = threadIdx.x;
    if (tid < NGATES * 12) sg[tid] = g_gates[tid];
    __syncthreads();

    int t = blockIdx.x * blockDim.x + tid;
    if (t >= half) return;
    int b0 = t, b1 = t + half;

    float4 xa = reinterpret_cast<const float4*>(x)[b0];
    float4 xb = reinterpret_cast<const float4*>(x)[b1];
    float xA[4] = {xa.x, xa.y, xa.z, xa.w};
    float xB[4] = {xb.x, xb.y, xb.z, xb.w};

    const float PI_F = 3.14159265358979323846f;

    // Per-qubit 2-vectors: v = Rot0_q * RZ(xn) * RY(2*xn) * |0>
    C2 v[4][2];
#pragma unroll
    for (int q = 0; q < 4; q++) {
        float br0[2], bi0[2], br1[2], bi1[2];
#pragma unroll
        for (int smp = 0; smp < 2; smp++) {
            float xv = smp ? xB[q] : xA[q];
            // tanh(x) = 1 - 2/(e^{2x}+1); saturates correctly at +/-inf
            float ex = __expf(2.0f * xv);
            float tnh = 1.0f - 2.0f / (ex + 1.0f);
            float xn = PI_F * tnh;                  // |xn| <= pi
            float sx, cx, sh, ch;
            __sincosf(xn, &sx, &cx);                // RY(2xn)|0> = [cos xn, sin xn]
            __sincosf(0.5f * xn, &sh, &ch);         // e^{-+ i xn/2}
            br0[smp] = cx * ch;  bi0[smp] = -cx * sh;
            br1[smp] = sx * ch;  bi1[smp] =  sx * sh;
        }
        C2 base0, base1;
        base0.r = pk2(br0[0], br0[1]); base0.i = pk2(bi0[0], bi0[1]);
        base1.r = pk2(br1[0], br1[1]); base1.i = pk2(bi1[0], bi1[1]);
        const u64* G = &sg[q * 12];                 // layer-0 gate, qubit q
        v[q][0] = cmulc(G[0], G[1], G[2], base0); cfmac(v[q][0], G[3], G[4], G[5], base1);
        v[q][1] = cmulc(G[6], G[7], G[8], base0); cfmac(v[q][1], G[9], G[10], G[11], base1);
    }

    // Product state s = v0 (x) v1 (x) v2 (x) v3, index j = q0*8+q1*4+q2*2+q3
    C2 u01[4], u23[4], st[16];
#pragma unroll
    for (int a = 0; a < 2; a++)
#pragma unroll
        for (int b = 0; b < 2; b++) {
            u01[a * 2 + b] = cmul(v[0][a], v[1][b]);
            u23[a * 2 + b] = cmul(v[2][a], v[3][b]);
        }
#pragma unroll
    for (int p = 0; p < 4; p++)
#pragma unroll
        for (int qq = 0; qq < 4; qq++)
            st[p * 4 + qq] = cmul(u01[p], u23[qq]);

    // ring (free permutation) -> layer-1 gates -> ring -> layer-2 gates -> ring
#pragma unroll
    for (int layer = 1; layer <= 3; layer++) {
        {   // CNOT ring: q1^=q0; q2^=q1; q3^=q2; q0^=q3 (compile-time renaming)
            C2 tmp[16];
#pragma unroll
            for (int j = 0; j < 16; j++) {
                int q0 = (j >> 3) & 1, q1 = (j >> 2) & 1, q2 = (j >> 1) & 1, q3 = j & 1;
                int n1 = q1 ^ q0, n2 = q2 ^ n1, n3 = q3 ^ n2, n0 = q0 ^ n3;
                tmp[(n0 << 3) | (n1 << 2) | (n2 << 1) | n3] = st[j];
            }
#pragma unroll
            for (int j = 0; j < 16; j++) st[j] = tmp[j];
        }
        if (layer == 3) break;
#pragma unroll
        for (int q = 0; q < 4; q++) {
            const u64* Gp = &sg[(layer * 4 + q) * 12];
            u64 G0 = Gp[0], G1 = Gp[1], G2 = Gp[2], G3 = Gp[3], G4 = Gp[4], G5 = Gp[5];
            u64 G6 = Gp[6], G7 = Gp[7], G8 = Gp[8], G9 = Gp[9], G10 = Gp[10], G11 = Gp[11];
            int stride = 8 >> q;
#pragma unroll
            for (int j = 0; j < 16; j++) {
                if (j & stride) continue;
                C2 s0 = st[j], s1 = st[j | stride];
                C2 n0 = cmulc(G0, G1, G2, s0); cfmac(n0, G3, G4, G5, s1);
                C2 n1 = cmulc(G6, G7, G8, s0); cfmac(n1, G9, G10, G11, s1);
                st[j] = n0; st[j | stride] = n1;
            }
        }
    }

    // probs + signed sums: <Z_q> = sum_j (1 - 2*bit_q(j)) |st_j|^2
    u64 p[16];
#pragma unroll
    for (int j = 0; j < 16; j++)
        p[j] = f2fma(st[j].i, st[j].i, f2mul(st[j].r, st[j].r));

    float evA[4], evB[4];
#pragma unroll
    for (int q = 0; q < 4; q++) {
        int mask = 8 >> q;
        u64 sp = 0, sn = 0;
        bool fp = true, fn = true;
#pragma unroll
        for (int j = 0; j < 16; j++) {
            if (j & mask) { sn = fn ? p[j] : f2add(sn, p[j]); fn = false; }
            else          { sp = fp ? p[j] : f2add(sp, p[j]); fp = false; }
        }
        u64 ev = f2add(sp, f2neg(sn));
        upk2(ev, evA[q], evB[q]);
    }

    reinterpret_cast<float4*>(out)[b0] = make_float4(evA[0], evA[1], evA[2], evA[3]);
    reinterpret_cast<float4*>(out)[b1] = make_float4(evB[0], evB[1], evB[2], evB[3]);
}

extern "C" void kernel_launch(void* const* d_in, const int* in_sizes, int n_in,
                              void* d_out, int out_size) {
    const float* x  = (const float*)d_in[0];   // [B, 4] fp32
    const float* qw = (const float*)d_in[1];   // [3, 4, 3] fp32
    float* out = (float*)d_out;                // [B, 4] fp32
    int B = in_sizes[0] / 4;
    int half = B >> 1;
    prep_kernel<<<1, 32>>>(qw);
    int threads = 256;
    int blocks = (half + threads - 1) / threads;
    qlayer_kernel<<<blocks, threads>>>(x, out, half);
}

// round 5
// speedup vs baseline: 1.2362x; 1.2362x over previous
#include <cuda_runtime.h>
#include <cuda_bf16.h>

typedef unsigned long long u64;
typedef unsigned int u32;
typedef unsigned short u16;

// ---------------- device globals (prep -> main) ----------------
__device__ u64 g_gates0[48];     // layer-0 Rot gates, dup-packed f32x2
__device__ uint2 gBF[16][32];    // B fragments: [0..7]=Whi (kt*4+nt), [8..15]=Wlo

// ---------------- packed f32x2 helpers ----------------
__device__ __forceinline__ u64 pk2(float a, float b) {
    u64 r; asm("mov.b64 %0, {%1, %2};" : "=l"(r) : "f"(a), "f"(b)); return r;
}
__device__ __forceinline__ void upk2(u64 v, float& a, float& b) {
    asm("mov.b64 {%0, %1}, %2;" : "=f"(a), "=f"(b) : "l"(v));
}
__device__ __forceinline__ u64 f2fma(u64 a, u64 b, u64 c) {
    u64 d; asm("fma.rn.f32x2 %0, %1, %2, %3;" : "=l"(d) : "l"(a), "l"(b), "l"(c)); return d;
}
__device__ __forceinline__ u64 f2mul(u64 a, u64 b) {
    u64 d; asm("mul.rn.f32x2 %0, %1, %2;" : "=l"(d) : "l"(a), "l"(b)); return d;
}
__device__ __forceinline__ u64 f2neg(u64 a) { return a ^ 0x8000000080000000ULL; }

struct C2 { u64 r, i; };

__device__ __forceinline__ C2 cmul(const C2& a, const C2& b) {
    C2 o;
    o.r = f2fma(f2neg(a.i), b.i, f2mul(a.r, b.r));
    o.i = f2fma(a.i, b.r, f2mul(a.r, b.i));
    return o;
}
__device__ __forceinline__ C2 cmulc(u64 ur, u64 ui, u64 uni, const C2& z) {
    C2 o;
    o.r = f2fma(uni, z.i, f2mul(ur, z.r));
    o.i = f2fma(ur, z.i, f2mul(ui, z.r));
    return o;
}
__device__ __forceinline__ void cfmac(C2& acc, u64 ur, u64 ui, u64 uni, const C2& z) {
    acc.r = f2fma(ur, z.r, acc.r);
    acc.r = f2fma(uni, z.i, acc.r);
    acc.i = f2fma(ui, z.r, acc.i);
    acc.i = f2fma(ur, z.i, acc.i);
}

__device__ __forceinline__ u32 smem_u32(const void* p) {
    u32 a;
    asm("{ .reg .u64 t; cvta.to.shared.u64 t, %1; cvt.u32.u64 %0, t; }" : "=r"(a) : "l"(p));
    return a;
}

// rn bf16 bits (manual, toolchain-safe)
__device__ __forceinline__ u16 bfbits(float f) {
    u32 u = __float_as_uint(f);
    u32 r = u + 0x7fffu + ((u >> 16) & 1u);
    return (u16)(r >> 16);
}
__device__ __forceinline__ float bf2f(u16 b) { return __uint_as_float(((u32)b) << 16); }

__device__ __forceinline__ int permf(int j) {
    int q0 = (j >> 3) & 1, q1 = (j >> 2) & 1, q2 = (j >> 1) & 1, q3 = j & 1;
    int n1 = q1 ^ q0, n2 = q2 ^ n1, n3 = q3 ^ n2, n0 = q0 ^ n3;
    return (n0 << 3) | (n1 << 2) | (n2 << 1) | n3;
}

// ---------------- prep: gates + W matrix + HMMA B fragments ----------------
__global__ void prep_kernel(const float* __restrict__ qw) {
    __shared__ float2 sG[12][4];
    __shared__ float Wsm[32][32];
    int tid = threadIdx.x;   // 32 threads
    if (tid < 12) {
        float phi = qw[3 * tid], th = qw[3 * tid + 1], om = qw[3 * tid + 2];
        float s, c; sincosf(0.5f * th, &s, &c);
        float a = 0.5f * (phi + om), b = 0.5f * (phi - om);
        float sa, ca, sb, cb;
        sincosf(a, &sa, &ca); sincosf(b, &sb, &cb);
        sG[tid][0] = make_float2( c * ca, -c * sa);
        sG[tid][1] = make_float2(-s * cb, -s * sb);
        sG[tid][2] = make_float2( s * cb, -s * sb);
        sG[tid][3] = make_float2( c * ca,  c * sa);
    }
    __syncthreads();
    if (tid < 4) {
        for (int e = 0; e < 4; e++) {
            float re = sG[tid][e].x, im = sG[tid][e].y;
            g_gates0[tid * 12 + e * 3 + 0] = pk2(re, re);
            g_gates0[tid * 12 + e * 3 + 1] = pk2(im, im);
            g_gates0[tid * 12 + e * 3 + 2] = pk2(-im, -im);
        }
    }
    if (tid < 16) {
        // evolve basis column `tid` through P1, G1, P2, G2, P3 -> column of U
        float2 col[16], tmp[16];
        for (int j = 0; j < 16; j++) col[j] = make_float2(0.f, 0.f);
        col[permf(tid)] = make_float2(1.f, 0.f);
        for (int l = 1; l <= 2; l++) {
            for (int q = 0; q < 4; q++) {
                int s = 8 >> q;
                float2 u00 = sG[l*4+q][0], u01 = sG[l*4+q][1];
                float2 u10 = sG[l*4+q][2], u11 = sG[l*4+q][3];
                for (int j = 0; j < 16; j++) if (!(j & s)) {
                    float2 a = col[j], b = col[j | s];
                    col[j] = make_float2(u00.x*a.x - u00.y*a.y + u01.x*b.x - u01.y*b.y,
                                         u00.x*a.y + u00.y*a.x + u01.x*b.y + u01.y*b.x);
                    col[j|s] = make_float2(u10.x*a.x - u10.y*a.y + u11.x*b.x - u11.y*b.y,
                                           u10.x*a.y + u10.y*a.x + u11.x*b.y + u11.y*b.x);
                }
            }
            for (int j = 0; j < 16; j++) tmp[permf(j)] = col[j];
            for (int j = 0; j < 16; j++) col[j] = tmp[j];
        }
        // W[n][k]: real 32x32: [[Ur, -Ui],[Ui, Ur]], this thread owns cols tid, tid+16
        for (int n = 0; n < 16; n++) {
            Wsm[n][tid]           =  col[n].x;
            Wsm[n + 16][tid]      =  col[n].y;
            Wsm[n][tid + 16]      = -col[n].y;
            Wsm[n + 16][tid + 16] =  col[n].x;
        }
    }
    __syncthreads();
    // emit per-lane mma.sync B fragments (k16n8, col-major: b0={B[k0],B[k0+1]}, b1={B[k0+8],B[k0+9]})
    // B[k][n] = W[n][k]; hi part for frags 0..7, lo residual for frags 8..15
    int t = tid & 3, g = tid >> 2;
    for (int kt = 0; kt < 2; kt++)
        for (int nt = 0; nt < 4; nt++) {
            int n = nt * 8 + g;
            int k0 = kt * 16 + 2 * t;
            u16 hb[4], lb[4];
            int ks[4] = {k0, k0 + 1, k0 + 8, k0 + 9};
            for (int i = 0; i < 4; i++) {
                float w = Wsm[n][ks[i]];
                hb[i] = bfbits(w);
                lb[i] = bfbits(w - bf2f(hb[i]));
            }
            gBF[kt*4+nt][tid]     = make_uint2((u32)hb[0] | ((u32)hb[1] << 16),
                                               (u32)hb[2] | ((u32)hb[3] << 16));
            gBF[8+kt*4+nt][tid]   = make_uint2((u32)lb[0] | ((u32)lb[1] << 16),
                                               (u32)lb[2] | ((u32)lb[3] << 16));
        }
}

// ---------------- warp-mma primitives ----------------
__device__ __forceinline__ void mma16816(float* c, const u32* a, uint2 b) {
    asm("mma.sync.aligned.m16n8k16.row.col.f32.bf16.bf16.f32 "
        "{%0,%1,%2,%3}, {%4,%5,%6,%7}, {%8,%9}, {%0,%1,%2,%3};"
        : "+f"(c[0]), "+f"(c[1]), "+f"(c[2]), "+f"(c[3])
        : "r"(a[0]), "r"(a[1]), "r"(a[2]), "r"(a[3]), "r"(b.x), "r"(b.y));
}
__device__ __forceinline__ void ldmA(u32* a, u32 addr) {
    asm volatile("ldmatrix.sync.aligned.m8n8.x4.shared.b16 {%0,%1,%2,%3}, [%4];"
        : "=r"(a[0]), "=r"(a[1]), "=r"(a[2]), "=r"(a[3]) : "r"(addr) : "memory");
}

// 32 fp32 -> row of 64 bf16 [hi(32)|lo(32)], XOR-swizzled 16B chunks, stride 128B
__device__ __forceinline__ void storeRow(const float* v, char* base, int r) {
    u32 hw[16], lw[16];
#pragma unroll
    for (int i = 0; i < 16; i++) {
        float v0 = v[2 * i], v1 = v[2 * i + 1];
        u32 b0 = __float_as_uint(v0), b1 = __float_as_uint(v1);
        hw[i] = __byte_perm(b0, b1, 0x7632);             // truncated bf16 pair
        float r0 = v0 - __uint_as_float(b0 & 0xFFFF0000u);
        float r1 = v1 - __uint_as_float(b1 & 0xFFFF0000u);
        lw[i] = __byte_perm(__float_as_uint(r0), __float_as_uint(r1), 0x7632);
    }
    char* rp = base + r * 128;
    int rx = r & 7;
#pragma unroll
    for (int c = 0; c < 4; c++)
        *(uint4*)(rp + ((c ^ rx) << 4)) = make_uint4(hw[4*c], hw[4*c+1], hw[4*c+2], hw[4*c+3]);
#pragma unroll
    for (int c = 4; c < 8; c++) {
        int i = 4 * (c - 4);
        *(uint4*)(rp + ((c ^ rx) << 4)) = make_uint4(lw[i], lw[i+1], lw[i+2], lw[i+3]);
    }
}

// ---------------- main persistent kernel ----------------
__global__ void __launch_bounds__(128, 4) qlayer_mma(const float* __restrict__ x,
                                                     float* __restrict__ out,
                                                     int nGroups) {
    __shared__ __align__(128) char sA[4][8192];   // per-warp 64 rows x 128B
    __shared__ uint2 sBF[16][32];
    __shared__ u64 sg[48];

    int tid = threadIdx.x, lane = tid & 31, wid = tid >> 5;
    for (int i = tid; i < 512; i += 128) ((uint2*)sBF)[i] = ((const uint2*)gBF)[i];
    if (tid < 48) sg[tid] = g_gates0[tid];
    __syncthreads();

    u32 aBase = smem_u32(sA[wid]);
    char* aPtr = sA[wid];
    const float PI_F = 3.14159265358979323846f;
    const int t4 = lane & 3;
    const int rbase = lane & 15;
    const int khalf = (lane >> 4) & 1;

    for (int grp = blockIdx.x; grp < nGroups; grp += gridDim.x) {
        int s0 = grp * 256 + wid * 64 + lane;

        // ---- build product state after encoding + layer-0 Rot (2 samples, f32x2) ----
        float4 xa = ((const float4*)x)[s0];
        float4 xb = ((const float4*)x)[s0 + 32];
        float xA[4] = {xa.x, xa.y, xa.z, xa.w};
        float xB[4] = {xb.x, xb.y, xb.z, xb.w};

        C2 v[4][2];
#pragma unroll
        for (int q = 0; q < 4; q++) {
            float br0[2], bi0[2], br1[2], bi1[2];
#pragma unroll
            for (int smp = 0; smp < 2; smp++) {
                float xv = smp ? xB[q] : xA[q];
                float ex = __expf(2.0f * xv);
                float tnh = 1.0f - 2.0f / (ex + 1.0f);
                float xn = PI_F * tnh;
                float sh, ch;
                __sincosf(0.5f * xn, &sh, &ch);
                float sx = 2.0f * sh * ch;          // sin(xn)
                float cx = 1.0f - 2.0f * sh * sh;   // cos(xn)
                br0[smp] = cx * ch;  bi0[smp] = -cx * sh;
                br1[smp] = sx * ch;  bi1[smp] =  sx * sh;
            }
            C2 b0p, b1p;
            b0p.r = pk2(br0[0], br0[1]); b0p.i = pk2(bi0[0], bi0[1]);
            b1p.r = pk2(br1[0], br1[1]); b1p.i = pk2(bi1[0], bi1[1]);
            const u64* G = &sg[q * 12];
            v[q][0] = cmulc(G[0], G[1], G[2], b0p); cfmac(v[q][0], G[3], G[4], G[5], b1p);
            v[q][1] = cmulc(G[6], G[7], G[8], b0p); cfmac(v[q][1], G[9], G[10], G[11], b1p);
        }
        C2 u01[4], u23[4], st[16];
#pragma unroll
        for (int a = 0; a < 2; a++)
#pragma unroll
            for (int b = 0; b < 2; b++) {
                u01[a * 2 + b] = cmul(v[0][a], v[1][b]);
                u23[a * 2 + b] = cmul(v[2][a], v[3][b]);
            }
#pragma unroll
        for (int p = 0; p < 4; p++)
#pragma unroll
            for (int qq = 0; qq < 4; qq++)
                st[p * 4 + qq] = cmul(u01[p], u23[qq]);

        // ---- unpack, split, store A rows ----
        float vA[32], vB[32];
#pragma unroll
        for (int j = 0; j < 16; j++) {
            upk2(st[j].r, vA[j], vB[j]);
            upk2(st[j].i, vA[16 + j], vB[16 + j]);
        }
        storeRow(vA, aPtr, lane);
        storeRow(vB, aPtr, lane + 32);
        __syncwarp();

        uint2 bf[16];
#pragma unroll
        for (int f = 0; f < 16; f++) bf[f] = sBF[f][lane];

#pragma unroll
        for (int mt = 0; mt < 4; mt++) {
            int r = mt * 16 + rbase;
            u32 rowAddr = aBase + (u32)(r * 128);
            int rx = r & 7;
            u32 fr[4][4];
#pragma unroll
            for (int kt = 0; kt < 4; kt++)
                ldmA(fr[kt], rowAddr + (u32)(((kt * 2 + khalf) ^ rx) << 4));

            float acc[4][4];
#pragma unroll
            for (int nt = 0; nt < 4; nt++)
                acc[nt][0] = acc[nt][1] = acc[nt][2] = acc[nt][3] = 0.f;
#pragma unroll
            for (int nt = 0; nt < 4; nt++) {
                mma16816(acc[nt], fr[0], bf[nt]);        // hi * Whi (k 0..15)
                mma16816(acc[nt], fr[1], bf[4 + nt]);    // hi * Whi (k 16..31)
                mma16816(acc[nt], fr[2], bf[nt]);        // lo * Whi
                mma16816(acc[nt], fr[3], bf[4 + nt]);
                mma16816(acc[nt], fr[0], bf[8 + nt]);    // hi * Wlo
                mma16816(acc[nt], fr[1], bf[12 + nt]);
            }

            // ---- epilogue: p_j = Re^2+Im^2 (cols j and j+16 both local), signed Z sums ----
            float p1a = fmaf(acc[0][0], acc[0][0], acc[2][0] * acc[2][0]);  // j=2t,   row g
            float p2a = fmaf(acc[0][1], acc[0][1], acc[2][1] * acc[2][1]);  // j=2t+1
            float p3a = fmaf(acc[1][0], acc[1][0], acc[3][0] * acc[3][0]);  // j=2t+8
            float p4a = fmaf(acc[1][1], acc[1][1], acc[3][1] * acc[3][1]);  // j=2t+9
            float p1b = fmaf(acc[0][2], acc[0][2], acc[2][2] * acc[2][2]);  // row g+8
            float p2b = fmaf(acc[0][3], acc[0][3], acc[2][3] * acc[2][3]);
            float p3b = fmaf(acc[1][2], acc[1][2], acc[3][2] * acc[3][2]);
            float p4b = fmaf(acc[1][3], acc[1][3], acc[3][3] * acc[3][3]);

            float Sa = (p1a + p2a) + (p3a + p4a), Sb = (p1b + p2b) + (p3b + p4b);
            float e0a = (p1a + p2a) - (p3a + p4a), e0b = (p1b + p2b) - (p3b + p4b);
            float e3a = (p1a - p2a) + (p3a - p4a), e3b = (p1b - p2b) + (p3b - p4b);
            float e1a = (t4 < 2) ? Sa : -Sa,  e1b = (t4 < 2) ? Sb : -Sb;
            float e2a = (t4 & 1) ? -Sa : Sa,  e2b = (t4 & 1) ? -Sb : Sb;

#pragma unroll
            for (int m = 1; m <= 2; m <<= 1) {
                e0a += __shfl_xor_sync(0xffffffffu, e0a, m);
                e1a += __shfl_xor_sync(0xffffffffu, e1a, m);
                e2a += __shfl_xor_sync(0xffffffffu, e2a, m);
                e3a += __shfl_xor_sync(0xffffffffu, e3a, m);
                e0b += __shfl_xor_sync(0xffffffffu, e0b, m);
                e1b += __shfl_xor_sync(0xffffffffu, e1b, m);
                e2b += __shfl_xor_sync(0xffffffffu, e2b, m);
                e3b += __shfl_xor_sync(0xffffffffu, e3b, m);
            }
            if (t4 == mt) {
                int row0 = grp * 256 + wid * 64 + mt * 16 + (lane >> 2);
                ((float4*)out)[row0]     = make_float4(e0a, e1a, e2a, e3a);
                ((float4*)out)[row0 + 8] = make_float4(e0b, e1b, e2b, e3b);
            }
        }
        __syncwarp();   // ldmatrix reads done before next iteration's stores
    }
}

extern "C" void kernel_launch(void* const* d_in, const int* in_sizes, int n_in,
                              void* d_out, int out_size) {
    const float* x  = (const float*)d_in[0];   // [B, 4]
    const float* qw = (const float*)d_in[1];   // [3, 4, 3]
    float* out = (float*)d_out;                // [B, 4]
    int B = in_sizes[0] / 4;
    int nGroups = B / 256;
    prep_kernel<<<1, 32>>>(qw);
    qlayer_mma<<<592, 128>>>(x, out, nGroups);
}